// round 13
// baseline (speedup 1.0000x reference)
#include <cuda_runtime.h>
#include <cuda_bf16.h>
#include <math.h>
#include <stdint.h>

#define BATCH 2048
#define UNITS 512
#define FEAT 3
#define SEQ 64
#define OUT_NOTES 64
#define ZCOLS 2048

#define BM 128
#define BN 256
#define KC 32
#define NSTG 4
#define NCH 48            // 3 split-segments x 16 k-chunks
#define THREADS 256

#define ROWB 80           // smem row stride (64B data + 16B pad: conflict-free ldmatrix)
#define A_ST (BM * ROWB)            // 10240
#define B_ST (BN * ROWB)            // 20480
#define STG_BYTES (A_ST + B_ST)     // 30720
#define HDR 6144
#define ZLD 264                      // epilogue z-tile row stride (floats)
#define SMEM_BYTES (HDR + BM * ZLD * 4)   // 141312 (stages need HDR+122880, fits)

// Persistent state (no allocations allowed)
__device__ __nv_bfloat16 g_hhi[2][BATCH * UNITS];
__device__ __nv_bfloat16 g_hlo[2][BATCH * UNITS];
__device__ float g_c[2][BATCH * UNITS];
__device__ float g_pred[BATCH * FEAT];
__device__ __nv_bfloat16 g_whi[ZCOLS * UNITS];  // [n'][k], n' = unit*4+gate
__device__ __nv_bfloat16 g_wlo[ZCOLS * UNITS];

// ---------------- helpers ----------------
__device__ __forceinline__ void cpasync16(uint32_t dst, const void* src) {
    asm volatile("cp.async.cg.shared.global [%0], [%1], 16;" :: "r"(dst), "l"(src));
}
__device__ __forceinline__ void ldm4(uint32_t* r, uint32_t addr) {
    asm volatile("ldmatrix.sync.aligned.m8n8.x4.shared.b16 {%0,%1,%2,%3}, [%4];"
                 : "=r"(r[0]), "=r"(r[1]), "=r"(r[2]), "=r"(r[3]) : "r"(addr));
}
__device__ __forceinline__ void mma16816(float* c, const uint32_t* a, uint32_t b0, uint32_t b1) {
    asm volatile("mma.sync.aligned.m16n8k16.row.col.f32.bf16.bf16.f32 "
                 "{%0,%1,%2,%3}, {%4,%5,%6,%7}, {%8,%9}, {%0,%1,%2,%3};"
                 : "+f"(c[0]), "+f"(c[1]), "+f"(c[2]), "+f"(c[3])
                 : "r"(a[0]), "r"(a[1]), "r"(a[2]), "r"(a[3]), "r"(b0), "r"(b1));
}
__device__ __forceinline__ float sigf(float x) { return 1.f / (1.f + expf(-x)); }

// ---------------- prep kernels ----------------
__global__ void zero_state_kernel() {
    const int n = BATCH * UNITS;
    for (int i = blockIdx.x * blockDim.x + threadIdx.x; i < n; i += gridDim.x * blockDim.x) {
        g_hhi[0][i] = __float2bfloat16(0.f);
        g_hlo[0][i] = __float2bfloat16(0.f);
        g_c[0][i] = 0.f;
    }
}

// Build permuted-transposed bf16 split of rec_kernel:
// n' = unit*4 + gate ; W'[n'][k] = Wr[k][gate*512 + unit]; hi = rn(w), lo = rn(w - hi).
__global__ void prep_w_kernel(const float* __restrict__ wr) {
    int t = blockIdx.x * blockDim.x + threadIdx.x;
    if (t >= ZCOLS * UNITS) return;
    int n = t >> 9, k = t & 511;
    int u = n >> 2, g = n & 3;
    float w = wr[(size_t)k * ZCOLS + g * UNITS + u];
    __nv_bfloat16 hi = __float2bfloat16(w);
    g_whi[t] = hi;
    g_wlo[t] = __float2bfloat16(w - __bfloat162float(hi));
}

// ---------------- fused LSTM step (mma.sync bf16, 3-split) ----------------
extern __shared__ __align__(16) char dynsmem[];

__global__ __launch_bounds__(THREADS, 1)
void lstm_mma_kernel(const float* __restrict__ x, int x_stride,
                     const float* __restrict__ wk,     // [3, 2048] gate-major cols
                     const float* __restrict__ bias,   // [2048]
                     int cur)
{
    const int tid = threadIdx.x;
    const int wid = tid >> 5, lane = tid & 31;
    const int wm = wid >> 2;                   // warp m half (0..1) -> 64 rows
    const int wn = wid & 3;                    // warp n quarter (0..3) -> 64 cols
    const int m0 = blockIdx.x * BM;
    const int n0 = blockIdx.y * BN;
    const int u0 = blockIdx.y * (BN / 4);

    const __nv_bfloat16* __restrict__ hhi = g_hhi[cur];
    const __nv_bfloat16* __restrict__ hlo = g_hlo[cur];
    const float* __restrict__ cin = g_c[cur];
    __nv_bfloat16* __restrict__ hhiO = g_hhi[cur ^ 1];
    __nv_bfloat16* __restrict__ hloO = g_hlo[cur ^ 1];
    float* __restrict__ cout = g_c[cur ^ 1];

    const uint32_t sbase = (uint32_t)__cvta_generic_to_shared(dynsmem);
    float* xs   = (float*)(dynsmem);           // [128][4]
    float* kcb0 = (float*)(dynsmem + 2048);    // [256]
    float* kcb1 = (float*)(dynsmem + 3072);
    float* kcb2 = (float*)(dynsmem + 4096);
    float* kcbB = (float*)(dynsmem + 5120);
    const uint32_t stg = sbase + HDR;

    // One-time per-CTA loads: x rows, kernel/bias columns (permuted col order)
    if (tid < BM) {
        const float* xr = x + (size_t)(m0 + tid) * x_stride;
        xs[tid * 4 + 0] = xr[0]; xs[tid * 4 + 1] = xr[1]; xs[tid * 4 + 2] = xr[2];
    }
    {
        int j = tid;                           // local permuted col
        int u = u0 + (j >> 2), g = j & 3;
        int col = g * UNITS + u;
        kcb0[j] = wk[col];
        kcb1[j] = wk[ZCOLS + col];
        kcb2[j] = wk[2 * ZCOLS + col];
        kcbB[j] = bias[col];
    }

    // Chunk loader: chunk i -> segment i>>4, k0 = (i&15)*32, stage i&3
    auto load_chunk = [&](int i) {
        const int seg = i >> 4;
        const int k0 = (i & 15) * KC;
        const __nv_bfloat16* aP = (seg == 2) ? hlo : hhi;
        const __nv_bfloat16* bP = (seg == 1) ? g_wlo : g_whi;
        const uint32_t sa = stg + (i & 3) * STG_BYTES;
        const uint32_t sb = sa + A_ST;
        // A: 128 rows x 64B. Thread -> row (t&127), chunk col (t>>7) and +2.
        {
            const int row = tid & 127, c = tid >> 7;
            const __nv_bfloat16* src = aP + (size_t)(m0 + row) * UNITS + k0 + c * 8;
            cpasync16(sa + row * ROWB + c * 16, src);
            cpasync16(sa + row * ROWB + (c + 2) * 16, src + 16);
        }
        // B: 256 rows x 64B. Thread -> row tid, 4 chunk cols.
        {
            const __nv_bfloat16* src = bP + (size_t)(n0 + tid) * UNITS + k0;
#pragma unroll
            for (int c = 0; c < 4; c++)
                cpasync16(sb + tid * ROWB + c * 16, src + c * 8);
        }
    };

    // ldmatrix per-lane offsets
    const uint32_t aLaneOff = (uint32_t)(((lane & 7) + ((lane >> 3) & 1) * 8) * ROWB
                                         + ((lane >> 4) & 1) * 16);
    const uint32_t bLaneOff = (uint32_t)(((lane & 7) + ((lane >> 4) & 1) * 8) * ROWB
                                         + ((lane >> 3) & 1) * 16);

    float acc[4][8][4];
#pragma unroll
    for (int mi = 0; mi < 4; mi++)
#pragma unroll
        for (int ni = 0; ni < 8; ni++)
#pragma unroll
            for (int q = 0; q < 4; q++) acc[mi][ni][q] = 0.f;

    // Prologue: stages 0..2
#pragma unroll
    for (int p = 0; p < NSTG - 1; p++) {
        load_chunk(p);
        asm volatile("cp.async.commit_group;" ::: "memory");
    }

    for (int j = 0; j < NCH; j++) {
        asm volatile("cp.async.wait_group 2;" ::: "memory");
        __syncthreads();
        if (j + NSTG - 1 < NCH) load_chunk(j + NSTG - 1);
        asm volatile("cp.async.commit_group;" ::: "memory");

        const uint32_t sa = stg + (j & 3) * STG_BYTES + (uint32_t)(wm * 64 * ROWB);
        const uint32_t sb = stg + (j & 3) * STG_BYTES + A_ST + (uint32_t)(wn * 64 * ROWB);
#pragma unroll
        for (int kk = 0; kk < 2; kk++) {
            const uint32_t ko = kk * 32;
            uint32_t aF[4][4], bF[4][4];
#pragma unroll
            for (int mi = 0; mi < 4; mi++)
                ldm4(aF[mi], sa + (uint32_t)(mi * 16 * ROWB) + aLaneOff + ko);
#pragma unroll
            for (int p = 0; p < 4; p++)
                ldm4(bF[p], sb + (uint32_t)(p * 16 * ROWB) + bLaneOff + ko);
#pragma unroll
            for (int mi = 0; mi < 4; mi++)
#pragma unroll
                for (int ni = 0; ni < 8; ni++)
                    mma16816(acc[mi][ni], aF[mi], bF[ni >> 1][(ni & 1) * 2],
                             bF[ni >> 1][(ni & 1) * 2 + 1]);
        }
    }

    // ---------------- epilogue ----------------
    __syncthreads();   // all warps done with stage smem; reuse as z-tile
    float* zs = (float*)(dynsmem + HDR);
#pragma unroll
    for (int mi = 0; mi < 4; mi++) {
        const int r = wm * 64 + mi * 16 + (lane >> 2);
#pragma unroll
        for (int ni = 0; ni < 8; ni++) {
            const int cN = wn * 64 + ni * 8 + 2 * (lane & 3);
            *(float2*)(zs + r * ZLD + cN)       = make_float2(acc[mi][ni][0], acc[mi][ni][1]);
            *(float2*)(zs + (r + 8) * ZLD + cN) = make_float2(acc[mi][ni][2], acc[mi][ni][3]);
        }
    }
    __syncthreads();

    const int uL = tid & 63;
    const int rB = tid >> 6;
    const float4 K0 = ((const float4*)kcb0)[uL];
    const float4 K1 = ((const float4*)kcb1)[uL];
    const float4 K2 = ((const float4*)kcb2)[uL];
    const float4 KB = ((const float4*)kcbB)[uL];
    const int uG = u0 + uL;
#pragma unroll 4
    for (int it = 0; it < 32; it++) {
        const int r = rB + it * 4;
        const float4 z = *(const float4*)(zs + r * ZLD + 4 * uL);
        const float x0 = xs[r * 4 + 0], x1 = xs[r * 4 + 1], x2 = xs[r * 4 + 2];
        const float zi = z.x + KB.x + x0 * K0.x + x1 * K1.x + x2 * K2.x;
        const float zf = z.y + KB.y + x0 * K0.y + x1 * K1.y + x2 * K2.y;
        const float zg = z.z + KB.z + x0 * K0.z + x1 * K1.z + x2 * K2.z;
        const float zo = z.w + KB.w + x0 * K0.w + x1 * K1.w + x2 * K2.w;
        const size_t idx = (size_t)(m0 + r) * UNITS + uG;
        const float cn = fmaf(sigf(zf), cin[idx], sigf(zi) * tanhf(zg));
        cout[idx] = cn;
        const float h = sigf(zo) * tanhf(cn);
        const __nv_bfloat16 hb = __float2bfloat16(h);
        hhiO[idx] = hb;
        hloO[idx] = __float2bfloat16(h - __bfloat162float(hb));
    }
}

// pred = h @ dense_w + dense_b; h = hi + lo. One warp per batch row.
__global__ void dense_kernel(int cur, const float* __restrict__ dw,
                             const float* __restrict__ db,
                             float* __restrict__ out_t)
{
    const int gwarp = (blockIdx.x * blockDim.x + threadIdx.x) >> 5;
    const int lane = threadIdx.x & 31;
    if (gwarp >= BATCH) return;
    const __nv_bfloat16* __restrict__ hh = g_hhi[cur] + (size_t)gwarp * UNITS;
    const __nv_bfloat16* __restrict__ hl = g_hlo[cur] + (size_t)gwarp * UNITS;
    float s0 = 0.f, s1 = 0.f, s2 = 0.f;
    for (int u = lane; u < UNITS; u += 32) {
        const float hv = __bfloat162float(hh[u]) + __bfloat162float(hl[u]);
        s0 = fmaf(hv, dw[u * 3 + 0], s0);
        s1 = fmaf(hv, dw[u * 3 + 1], s1);
        s2 = fmaf(hv, dw[u * 3 + 2], s2);
    }
#pragma unroll
    for (int o = 16; o; o >>= 1) {
        s0 += __shfl_down_sync(0xffffffffu, s0, o);
        s1 += __shfl_down_sync(0xffffffffu, s1, o);
        s2 += __shfl_down_sync(0xffffffffu, s2, o);
    }
    if (lane == 0) {
        const float p0 = s0 + db[0];
        const float p1 = s1 + db[1];
        const float p2 = s2 + db[2];
        out_t[gwarp * 3 + 0] = p0;
        out_t[gwarp * 3 + 1] = p1;
        out_t[gwarp * 3 + 2] = p2;
        g_pred[gwarp * 3 + 0] = p0;
        g_pred[gwarp * 3 + 1] = p1;
        g_pred[gwarp * 3 + 2] = p2;
    }
}

extern "C" void kernel_launch(void* const* d_in, const int* in_sizes, int n_in,
                              void* d_out, int out_size) {
    const float* inputs = (const float*)d_in[0];  // [B, S, F]
    const float* wk     = (const float*)d_in[1];  // [F, 4U]
    const float* wr     = (const float*)d_in[2];  // [U, 4U]
    const float* bias   = (const float*)d_in[3];  // [4U]
    const float* dw     = (const float*)d_in[4];  // [U, F]
    const float* db     = (const float*)d_in[5];  // [F]
    float* out = (float*)d_out;                   // [OUT_NOTES, B, F]

    cudaFuncSetAttribute(lstm_mma_kernel, cudaFuncAttributeMaxDynamicSharedMemorySize, SMEM_BYTES);

    float* pred_ptr = nullptr;
    cudaGetSymbolAddress((void**)&pred_ptr, g_pred);

    prep_w_kernel<<<(ZCOLS * UNITS + 255) / 256, 256>>>(wr);
    zero_state_kernel<<<256, 256>>>();

    const dim3 grid(BATCH / BM, ZCOLS / BN);   // 16 x 8
    int cur = 0;
    for (int t = 0; t < SEQ; t++) {
        lstm_mma_kernel<<<grid, THREADS, SMEM_BYTES>>>(inputs + t * FEAT, SEQ * FEAT, wk, bias, cur);
        cur ^= 1;
    }
    dense_kernel<<<BATCH / 8, 256>>>(cur, dw, db, out);
    for (int t = 1; t < OUT_NOTES; t++) {
        lstm_mma_kernel<<<grid, THREADS, SMEM_BYTES>>>(pred_ptr, FEAT, wk, bias, cur);
        cur ^= 1;
        dense_kernel<<<BATCH / 8, 256>>>(cur, dw, db, out + (size_t)t * BATCH * FEAT);
    }
}

// round 14
// speedup vs baseline: 1.0016x; 1.0016x over previous
#include <cuda_runtime.h>
#include <cuda_bf16.h>
#include <math.h>
#include <stdint.h>

#define BATCH 2048
#define UNITS 512
#define FEAT 3
#define SEQ 64
#define OUT_NOTES 64
#define ZCOLS 2048

#define BM 128
#define BN 256
#define KC 32
#define NSTG 4
#define NCH 48            // 3 split-segments x 16 k-chunks
#define THREADS 256

#define ROWB 80           // smem row stride (64B data + 16B pad: conflict-free ldmatrix)
#define A_ST (BM * ROWB)            // 10240
#define B_ST (BN * ROWB)            // 20480
#define STG_BYTES (A_ST + B_ST)     // 30720
#define HDR 6144
#define ZLD 264                      // epilogue z-tile row stride (floats)
#define SMEM_BYTES (HDR + BM * ZLD * 4)   // 141312 (stages need HDR+122880, fits)

// Persistent state (no allocations allowed)
__device__ __nv_bfloat16 g_hhi[2][BATCH * UNITS];
__device__ __nv_bfloat16 g_hlo[2][BATCH * UNITS];
__device__ float g_c[2][BATCH * UNITS];
__device__ float g_pred[BATCH * FEAT];
__device__ __nv_bfloat16 g_whi[ZCOLS * UNITS];  // [n'][k], n' = unit*4+gate
__device__ __nv_bfloat16 g_wlo[ZCOLS * UNITS];

// ---------------- helpers ----------------
__device__ __forceinline__ void cpasync16(uint32_t dst, const void* src) {
    asm volatile("cp.async.cg.shared.global [%0], [%1], 16;" :: "r"(dst), "l"(src));
}
__device__ __forceinline__ void ldm4(uint32_t* r, uint32_t addr) {
    asm volatile("ldmatrix.sync.aligned.m8n8.x4.shared.b16 {%0,%1,%2,%3}, [%4];"
                 : "=r"(r[0]), "=r"(r[1]), "=r"(r[2]), "=r"(r[3]) : "r"(addr));
}
__device__ __forceinline__ void mma16816(float* c, const uint32_t* a, uint32_t b0, uint32_t b1) {
    asm volatile("mma.sync.aligned.m16n8k16.row.col.f32.bf16.bf16.f32 "
                 "{%0,%1,%2,%3}, {%4,%5,%6,%7}, {%8,%9}, {%0,%1,%2,%3};"
                 : "+f"(c[0]), "+f"(c[1]), "+f"(c[2]), "+f"(c[3])
                 : "r"(a[0]), "r"(a[1]), "r"(a[2]), "r"(a[3]), "r"(b0), "r"(b1));
}
__device__ __forceinline__ float sigf(float x) { return 1.f / (1.f + expf(-x)); }

// ---------------- prep kernels ----------------
__global__ void zero_state_kernel() {
    const int n = BATCH * UNITS;
    for (int i = blockIdx.x * blockDim.x + threadIdx.x; i < n; i += gridDim.x * blockDim.x) {
        g_hhi[0][i] = __float2bfloat16(0.f);
        g_hlo[0][i] = __float2bfloat16(0.f);
        g_c[0][i] = 0.f;
    }
}

// Build permuted-transposed bf16 split of rec_kernel:
// n' = unit*4 + gate ; W'[n'][k] = Wr[k][gate*512 + unit]; hi = rn(w), lo = rn(w - hi).
__global__ void prep_w_kernel(const float* __restrict__ wr) {
    int t = blockIdx.x * blockDim.x + threadIdx.x;
    if (t >= ZCOLS * UNITS) return;
    int n = t >> 9, k = t & 511;
    int u = n >> 2, g = n & 3;
    float w = wr[(size_t)k * ZCOLS + g * UNITS + u];
    __nv_bfloat16 hi = __float2bfloat16(w);
    g_whi[t] = hi;
    g_wlo[t] = __float2bfloat16(w - __bfloat162float(hi));
}

// ---------------- fused LSTM step (mma.sync bf16, 3-split) ----------------
extern __shared__ __align__(16) char dynsmem[];

__global__ __launch_bounds__(THREADS, 1)
void lstm_mma_kernel(const float* __restrict__ x, int x_stride,
                     const float* __restrict__ wk,     // [3, 2048] gate-major cols
                     const float* __restrict__ bias,   // [2048]
                     int cur)
{
    const int tid = threadIdx.x;
    const int wid = tid >> 5, lane = tid & 31;
    const int wm = wid >> 2;                   // warp m half (0..1) -> 64 rows
    const int wn = wid & 3;                    // warp n quarter (0..3) -> 64 cols
    const int m0 = blockIdx.x * BM;
    const int n0 = blockIdx.y * BN;
    const int u0 = blockIdx.y * (BN / 4);

    const __nv_bfloat16* __restrict__ hhi = g_hhi[cur];
    const __nv_bfloat16* __restrict__ hlo = g_hlo[cur];
    const float* __restrict__ cin = g_c[cur];
    __nv_bfloat16* __restrict__ hhiO = g_hhi[cur ^ 1];
    __nv_bfloat16* __restrict__ hloO = g_hlo[cur ^ 1];
    float* __restrict__ cout = g_c[cur ^ 1];

    const uint32_t sbase = (uint32_t)__cvta_generic_to_shared(dynsmem);
    float* xs   = (float*)(dynsmem);           // [128][4]
    float* kcb0 = (float*)(dynsmem + 2048);    // [256]
    float* kcb1 = (float*)(dynsmem + 3072);
    float* kcb2 = (float*)(dynsmem + 4096);
    float* kcbB = (float*)(dynsmem + 5120);
    const uint32_t stg = sbase + HDR;

    // One-time per-CTA loads: x rows, kernel/bias columns (permuted col order)
    if (tid < BM) {
        const float* xr = x + (size_t)(m0 + tid) * x_stride;
        xs[tid * 4 + 0] = xr[0]; xs[tid * 4 + 1] = xr[1]; xs[tid * 4 + 2] = xr[2];
    }
    {
        int j = tid;                           // local permuted col
        int u = u0 + (j >> 2), g = j & 3;
        int col = g * UNITS + u;
        kcb0[j] = wk[col];
        kcb1[j] = wk[ZCOLS + col];
        kcb2[j] = wk[2 * ZCOLS + col];
        kcbB[j] = bias[col];
    }

    // Chunk loader: chunk i -> segment i>>4, k0 = (i&15)*32, stage i&3
    auto load_chunk = [&](int i) {
        const int seg = i >> 4;
        const int k0 = (i & 15) * KC;
        const __nv_bfloat16* aP = (seg == 2) ? hlo : hhi;
        const __nv_bfloat16* bP = (seg == 1) ? g_wlo : g_whi;
        const uint32_t sa = stg + (i & 3) * STG_BYTES;
        const uint32_t sb = sa + A_ST;
        // A: 128 rows x 64B. Thread -> row (t&127), chunk col (t>>7) and +2.
        {
            const int row = tid & 127, c = tid >> 7;
            const __nv_bfloat16* src = aP + (size_t)(m0 + row) * UNITS + k0 + c * 8;
            cpasync16(sa + row * ROWB + c * 16, src);
            cpasync16(sa + row * ROWB + (c + 2) * 16, src + 16);
        }
        // B: 256 rows x 64B. Thread -> row tid, 4 chunk cols.
        {
            const __nv_bfloat16* src = bP + (size_t)(n0 + tid) * UNITS + k0;
#pragma unroll
            for (int c = 0; c < 4; c++)
                cpasync16(sb + tid * ROWB + c * 16, src + c * 8);
        }
    };

    // ldmatrix per-lane offsets
    const uint32_t aLaneOff = (uint32_t)(((lane & 7) + ((lane >> 3) & 1) * 8) * ROWB
                                         + ((lane >> 4) & 1) * 16);
    const uint32_t bLaneOff = (uint32_t)(((lane & 7) + ((lane >> 4) & 1) * 8) * ROWB
                                         + ((lane >> 3) & 1) * 16);

    float acc[4][8][4];
#pragma unroll
    for (int mi = 0; mi < 4; mi++)
#pragma unroll
        for (int ni = 0; ni < 8; ni++)
#pragma unroll
            for (int q = 0; q < 4; q++) acc[mi][ni][q] = 0.f;

    // Prologue: stages 0..2
#pragma unroll
    for (int p = 0; p < NSTG - 1; p++) {
        load_chunk(p);
        asm volatile("cp.async.commit_group;" ::: "memory");
    }

    for (int j = 0; j < NCH; j++) {
        asm volatile("cp.async.wait_group 2;" ::: "memory");
        __syncthreads();
        if (j + NSTG - 1 < NCH) load_chunk(j + NSTG - 1);
        asm volatile("cp.async.commit_group;" ::: "memory");

        const uint32_t sa = stg + (j & 3) * STG_BYTES + (uint32_t)(wm * 64 * ROWB);
        const uint32_t sb = stg + (j & 3) * STG_BYTES + A_ST + (uint32_t)(wn * 64 * ROWB);
#pragma unroll
        for (int kk = 0; kk < 2; kk++) {
            const uint32_t ko = kk * 32;
            uint32_t aF[4][4], bF[4][4];
#pragma unroll
            for (int mi = 0; mi < 4; mi++)
                ldm4(aF[mi], sa + (uint32_t)(mi * 16 * ROWB) + aLaneOff + ko);
#pragma unroll
            for (int p = 0; p < 4; p++)
                ldm4(bF[p], sb + (uint32_t)(p * 16 * ROWB) + bLaneOff + ko);
#pragma unroll
            for (int mi = 0; mi < 4; mi++)
#pragma unroll
                for (int ni = 0; ni < 8; ni++)
                    mma16816(acc[mi][ni], aF[mi], bF[ni >> 1][(ni & 1) * 2],
                             bF[ni >> 1][(ni & 1) * 2 + 1]);
        }
    }

    // ---------------- epilogue ----------------
    __syncthreads();   // all warps done with stage smem; reuse as z-tile
    float* zs = (float*)(dynsmem + HDR);
#pragma unroll
    for (int mi = 0; mi < 4; mi++) {
        const int r = wm * 64 + mi * 16 + (lane >> 2);
#pragma unroll
        for (int ni = 0; ni < 8; ni++) {
            const int cN = wn * 64 + ni * 8 + 2 * (lane & 3);
            *(float2*)(zs + r * ZLD + cN)       = make_float2(acc[mi][ni][0], acc[mi][ni][1]);
            *(float2*)(zs + (r + 8) * ZLD + cN) = make_float2(acc[mi][ni][2], acc[mi][ni][3]);
        }
    }
    __syncthreads();

    const int uL = tid & 63;
    const int rB = tid >> 6;
    const float4 K0 = ((const float4*)kcb0)[uL];
    const float4 K1 = ((const float4*)kcb1)[uL];
    const float4 K2 = ((const float4*)kcb2)[uL];
    const float4 KB = ((const float4*)kcbB)[uL];
    const int uG = u0 + uL;
#pragma unroll 4
    for (int it = 0; it < 32; it++) {
        const int r = rB + it * 4;
        const float4 z = *(const float4*)(zs + r * ZLD + 4 * uL);
        const float x0 = xs[r * 4 + 0], x1 = xs[r * 4 + 1], x2 = xs[r * 4 + 2];
        const float zi = z.x + KB.x + x0 * K0.x + x1 * K1.x + x2 * K2.x;
        const float zf = z.y + KB.y + x0 * K0.y + x1 * K1.y + x2 * K2.y;
        const float zg = z.z + KB.z + x0 * K0.z + x1 * K1.z + x2 * K2.z;
        const float zo = z.w + KB.w + x0 * K0.w + x1 * K1.w + x2 * K2.w;
        const size_t idx = (size_t)(m0 + r) * UNITS + uG;
        const float cn = fmaf(sigf(zf), cin[idx], sigf(zi) * tanhf(zg));
        cout[idx] = cn;
        const float h = sigf(zo) * tanhf(cn);
        const __nv_bfloat16 hb = __float2bfloat16(h);
        hhiO[idx] = hb;
        hloO[idx] = __float2bfloat16(h - __bfloat162float(hb));
    }
}

// pred = h @ dense_w + dense_b; h = hi + lo. One warp per batch row.
__global__ void dense_kernel(int cur, const float* __restrict__ dw,
                             const float* __restrict__ db,
                             float* __restrict__ out_t)
{
    const int gwarp = (blockIdx.x * blockDim.x + threadIdx.x) >> 5;
    const int lane = threadIdx.x & 31;
    if (gwarp >= BATCH) return;
    const __nv_bfloat16* __restrict__ hh = g_hhi[cur] + (size_t)gwarp * UNITS;
    const __nv_bfloat16* __restrict__ hl = g_hlo[cur] + (size_t)gwarp * UNITS;
    float s0 = 0.f, s1 = 0.f, s2 = 0.f;
    for (int u = lane; u < UNITS; u += 32) {
        const float hv = __bfloat162float(hh[u]) + __bfloat162float(hl[u]);
        s0 = fmaf(hv, dw[u * 3 + 0], s0);
        s1 = fmaf(hv, dw[u * 3 + 1], s1);
        s2 = fmaf(hv, dw[u * 3 + 2], s2);
    }
#pragma unroll
    for (int o = 16; o; o >>= 1) {
        s0 += __shfl_down_sync(0xffffffffu, s0, o);
        s1 += __shfl_down_sync(0xffffffffu, s1, o);
        s2 += __shfl_down_sync(0xffffffffu, s2, o);
    }
    if (lane == 0) {
        const float p0 = s0 + db[0];
        const float p1 = s1 + db[1];
        const float p2 = s2 + db[2];
        out_t[gwarp * 3 + 0] = p0;
        out_t[gwarp * 3 + 1] = p1;
        out_t[gwarp * 3 + 2] = p2;
        g_pred[gwarp * 3 + 0] = p0;
        g_pred[gwarp * 3 + 1] = p1;
        g_pred[gwarp * 3 + 2] = p2;
    }
}

extern "C" void kernel_launch(void* const* d_in, const int* in_sizes, int n_in,
                              void* d_out, int out_size) {
    const float* inputs = (const float*)d_in[0];  // [B, S, F]
    const float* wk     = (const float*)d_in[1];  // [F, 4U]
    const float* wr     = (const float*)d_in[2];  // [U, 4U]
    const float* bias   = (const float*)d_in[3];  // [4U]
    const float* dw     = (const float*)d_in[4];  // [U, F]
    const float* db     = (const float*)d_in[5];  // [F]
    float* out = (float*)d_out;                   // [OUT_NOTES, B, F]

    cudaFuncSetAttribute(lstm_mma_kernel, cudaFuncAttributeMaxDynamicSharedMemorySize, SMEM_BYTES);

    float* pred_ptr = nullptr;
    cudaGetSymbolAddress((void**)&pred_ptr, g_pred);

    prep_w_kernel<<<(ZCOLS * UNITS + 255) / 256, 256>>>(wr);
    zero_state_kernel<<<256, 256>>>();

    const dim3 grid(BATCH / BM, ZCOLS / BN);   // 16 x 8
    int cur = 0;
    for (int t = 0; t < SEQ; t++) {
        lstm_mma_kernel<<<grid, THREADS, SMEM_BYTES>>>(inputs + t * FEAT, SEQ * FEAT, wk, bias, cur);
        cur ^= 1;
    }
    dense_kernel<<<BATCH / 8, 256>>>(cur, dw, db, out);
    for (int t = 1; t < OUT_NOTES; t++) {
        lstm_mma_kernel<<<grid, THREADS, SMEM_BYTES>>>(pred_ptr, FEAT, wk, bias, cur);
        cur ^= 1;
        dense_kernel<<<BATCH / 8, 256>>>(cur, dw, db, out + (size_t)t * BATCH * FEAT);
    }
}

// round 15
// speedup vs baseline: 1.0019x; 1.0003x over previous
#include <cuda_runtime.h>
#include <cuda_bf16.h>
#include <math.h>
#include <stdint.h>

#define BATCH 2048
#define UNITS 512
#define FEAT 3
#define SEQ 64
#define OUT_NOTES 64
#define ZCOLS 2048

#define BM 128
#define BN 256
#define KC 32
#define NSTG 4
#define NCH 48            // 3 split-segments x 16 k-chunks
#define THREADS 256

#define ROWB 80           // smem row stride (64B data + 16B pad: conflict-free ldmatrix)
#define A_ST (BM * ROWB)            // 10240
#define B_ST (BN * ROWB)            // 20480
#define STG_BYTES (A_ST + B_ST)     // 30720
#define HDR 6144
#define ZLD 264                      // epilogue z-tile row stride (floats)
#define SMEM_BYTES (HDR + BM * ZLD * 4)   // 141312 (stages need HDR+122880, fits)

// Persistent state (no allocations allowed)
__device__ __nv_bfloat16 g_hhi[2][BATCH * UNITS];
__device__ __nv_bfloat16 g_hlo[2][BATCH * UNITS];
__device__ float g_c[2][BATCH * UNITS];
__device__ float g_pred[BATCH * FEAT];
__device__ __nv_bfloat16 g_whi[ZCOLS * UNITS];  // [n'][k], n' = unit*4+gate
__device__ __nv_bfloat16 g_wlo[ZCOLS * UNITS];

// ---------------- helpers ----------------
__device__ __forceinline__ void cpasync16(uint32_t dst, const void* src) {
    asm volatile("cp.async.cg.shared.global [%0], [%1], 16;" :: "r"(dst), "l"(src));
}
__device__ __forceinline__ void ldm4(uint32_t* r, uint32_t addr) {
    asm volatile("ldmatrix.sync.aligned.m8n8.x4.shared.b16 {%0,%1,%2,%3}, [%4];"
                 : "=r"(r[0]), "=r"(r[1]), "=r"(r[2]), "=r"(r[3]) : "r"(addr));
}
__device__ __forceinline__ void mma16816(float* c, const uint32_t* a, uint32_t b0, uint32_t b1) {
    asm volatile("mma.sync.aligned.m16n8k16.row.col.f32.bf16.bf16.f32 "
                 "{%0,%1,%2,%3}, {%4,%5,%6,%7}, {%8,%9}, {%0,%1,%2,%3};"
                 : "+f"(c[0]), "+f"(c[1]), "+f"(c[2]), "+f"(c[3])
                 : "r"(a[0]), "r"(a[1]), "r"(a[2]), "r"(a[3]), "r"(b0), "r"(b1));
}
__device__ __forceinline__ float sigf(float x) { return 1.f / (1.f + expf(-x)); }

// ---------------- prep kernels ----------------
__global__ void zero_state_kernel() {
    const int n = BATCH * UNITS;
    for (int i = blockIdx.x * blockDim.x + threadIdx.x; i < n; i += gridDim.x * blockDim.x) {
        g_hhi[0][i] = __float2bfloat16(0.f);
        g_hlo[0][i] = __float2bfloat16(0.f);
        g_c[0][i] = 0.f;
    }
}

// Build permuted-transposed bf16 split of rec_kernel:
// n' = unit*4 + gate ; W'[n'][k] = Wr[k][gate*512 + unit]; hi = rn(w), lo = rn(w - hi).
__global__ void prep_w_kernel(const float* __restrict__ wr) {
    int t = blockIdx.x * blockDim.x + threadIdx.x;
    if (t >= ZCOLS * UNITS) return;
    int n = t >> 9, k = t & 511;
    int u = n >> 2, g = n & 3;
    float w = wr[(size_t)k * ZCOLS + g * UNITS + u];
    __nv_bfloat16 hi = __float2bfloat16(w);
    g_whi[t] = hi;
    g_wlo[t] = __float2bfloat16(w - __bfloat162float(hi));
}

// ---------------- fused LSTM step (mma.sync bf16, 3-split) ----------------
extern __shared__ __align__(16) char dynsmem[];

__global__ __launch_bounds__(THREADS, 1)
void lstm_mma_kernel(const float* __restrict__ x, int x_stride,
                     const float* __restrict__ wk,     // [3, 2048] gate-major cols
                     const float* __restrict__ bias,   // [2048]
                     int cur)
{
    const int tid = threadIdx.x;
    const int wid = tid >> 5, lane = tid & 31;
    const int wm = wid >> 2;                   // warp m half (0..1) -> 64 rows
    const int wn = wid & 3;                    // warp n quarter (0..3) -> 64 cols
    const int m0 = blockIdx.x * BM;
    const int n0 = blockIdx.y * BN;
    const int u0 = blockIdx.y * (BN / 4);

    const __nv_bfloat16* __restrict__ hhi = g_hhi[cur];
    const __nv_bfloat16* __restrict__ hlo = g_hlo[cur];
    const float* __restrict__ cin = g_c[cur];
    __nv_bfloat16* __restrict__ hhiO = g_hhi[cur ^ 1];
    __nv_bfloat16* __restrict__ hloO = g_hlo[cur ^ 1];
    float* __restrict__ cout = g_c[cur ^ 1];

    const uint32_t sbase = (uint32_t)__cvta_generic_to_shared(dynsmem);
    float* xs   = (float*)(dynsmem);           // [128][4]
    float* kcb0 = (float*)(dynsmem + 2048);    // [256]
    float* kcb1 = (float*)(dynsmem + 3072);
    float* kcb2 = (float*)(dynsmem + 4096);
    float* kcbB = (float*)(dynsmem + 5120);
    const uint32_t stg = sbase + HDR;

    // One-time per-CTA loads: x rows, kernel/bias columns (permuted col order)
    if (tid < BM) {
        const float* xr = x + (size_t)(m0 + tid) * x_stride;
        xs[tid * 4 + 0] = xr[0]; xs[tid * 4 + 1] = xr[1]; xs[tid * 4 + 2] = xr[2];
    }
    {
        int j = tid;                           // local permuted col
        int u = u0 + (j >> 2), g = j & 3;
        int col = g * UNITS + u;
        kcb0[j] = wk[col];
        kcb1[j] = wk[ZCOLS + col];
        kcb2[j] = wk[2 * ZCOLS + col];
        kcbB[j] = bias[col];
    }

    // Chunk loader: chunk i -> segment i>>4, k0 = (i&15)*32, stage i&3
    auto load_chunk = [&](int i) {
        const int seg = i >> 4;
        const int k0 = (i & 15) * KC;
        const __nv_bfloat16* aP = (seg == 2) ? hlo : hhi;
        const __nv_bfloat16* bP = (seg == 1) ? g_wlo : g_whi;
        const uint32_t sa = stg + (i & 3) * STG_BYTES;
        const uint32_t sb = sa + A_ST;
        // A: 128 rows x 64B. Thread -> row (t&127), chunk col (t>>7) and +2.
        {
            const int row = tid & 127, c = tid >> 7;
            const __nv_bfloat16* src = aP + (size_t)(m0 + row) * UNITS + k0 + c * 8;
            cpasync16(sa + row * ROWB + c * 16, src);
            cpasync16(sa + row * ROWB + (c + 2) * 16, src + 16);
        }
        // B: 256 rows x 64B. Thread -> row tid, 4 chunk cols.
        {
            const __nv_bfloat16* src = bP + (size_t)(n0 + tid) * UNITS + k0;
#pragma unroll
            for (int c = 0; c < 4; c++)
                cpasync16(sb + tid * ROWB + c * 16, src + c * 8);
        }
    };

    // ldmatrix per-lane offsets
    const uint32_t aLaneOff = (uint32_t)(((lane & 7) + ((lane >> 3) & 1) * 8) * ROWB
                                         + ((lane >> 4) & 1) * 16);
    const uint32_t bLaneOff = (uint32_t)(((lane & 7) + ((lane >> 4) & 1) * 8) * ROWB
                                         + ((lane >> 3) & 1) * 16);

    float acc[4][8][4];
#pragma unroll
    for (int mi = 0; mi < 4; mi++)
#pragma unroll
        for (int ni = 0; ni < 8; ni++)
#pragma unroll
            for (int q = 0; q < 4; q++) acc[mi][ni][q] = 0.f;

    // Prologue: stages 0..2
#pragma unroll
    for (int p = 0; p < NSTG - 1; p++) {
        load_chunk(p);
        asm volatile("cp.async.commit_group;" ::: "memory");
    }

    for (int j = 0; j < NCH; j++) {
        asm volatile("cp.async.wait_group 2;" ::: "memory");
        __syncthreads();
        if (j + NSTG - 1 < NCH) load_chunk(j + NSTG - 1);
        asm volatile("cp.async.commit_group;" ::: "memory");

        const uint32_t sa = stg + (j & 3) * STG_BYTES + (uint32_t)(wm * 64 * ROWB);
        const uint32_t sb = stg + (j & 3) * STG_BYTES + A_ST + (uint32_t)(wn * 64 * ROWB);
#pragma unroll
        for (int kk = 0; kk < 2; kk++) {
            const uint32_t ko = kk * 32;
            uint32_t aF[4][4], bF[4][4];
#pragma unroll
            for (int mi = 0; mi < 4; mi++)
                ldm4(aF[mi], sa + (uint32_t)(mi * 16 * ROWB) + aLaneOff + ko);
#pragma unroll
            for (int p = 0; p < 4; p++)
                ldm4(bF[p], sb + (uint32_t)(p * 16 * ROWB) + bLaneOff + ko);
#pragma unroll
            for (int mi = 0; mi < 4; mi++)
#pragma unroll
                for (int ni = 0; ni < 8; ni++)
                    mma16816(acc[mi][ni], aF[mi], bF[ni >> 1][(ni & 1) * 2],
                             bF[ni >> 1][(ni & 1) * 2 + 1]);
        }
    }

    // ---------------- epilogue ----------------
    __syncthreads();   // all warps done with stage smem; reuse as z-tile
    float* zs = (float*)(dynsmem + HDR);
#pragma unroll
    for (int mi = 0; mi < 4; mi++) {
        const int r = wm * 64 + mi * 16 + (lane >> 2);
#pragma unroll
        for (int ni = 0; ni < 8; ni++) {
            const int cN = wn * 64 + ni * 8 + 2 * (lane & 3);
            *(float2*)(zs + r * ZLD + cN)       = make_float2(acc[mi][ni][0], acc[mi][ni][1]);
            *(float2*)(zs + (r + 8) * ZLD + cN) = make_float2(acc[mi][ni][2], acc[mi][ni][3]);
        }
    }
    __syncthreads();

    const int uL = tid & 63;
    const int rB = tid >> 6;
    const float4 K0 = ((const float4*)kcb0)[uL];
    const float4 K1 = ((const float4*)kcb1)[uL];
    const float4 K2 = ((const float4*)kcb2)[uL];
    const float4 KB = ((const float4*)kcbB)[uL];
    const int uG = u0 + uL;
#pragma unroll 4
    for (int it = 0; it < 32; it++) {
        const int r = rB + it * 4;
        const float4 z = *(const float4*)(zs + r * ZLD + 4 * uL);
        const float x0 = xs[r * 4 + 0], x1 = xs[r * 4 + 1], x2 = xs[r * 4 + 2];
        const float zi = z.x + KB.x + x0 * K0.x + x1 * K1.x + x2 * K2.x;
        const float zf = z.y + KB.y + x0 * K0.y + x1 * K1.y + x2 * K2.y;
        const float zg = z.z + KB.z + x0 * K0.z + x1 * K1.z + x2 * K2.z;
        const float zo = z.w + KB.w + x0 * K0.w + x1 * K1.w + x2 * K2.w;
        const size_t idx = (size_t)(m0 + r) * UNITS + uG;
        const float cn = fmaf(sigf(zf), cin[idx], sigf(zi) * tanhf(zg));
        cout[idx] = cn;
        const float h = sigf(zo) * tanhf(cn);
        const __nv_bfloat16 hb = __float2bfloat16(h);
        hhiO[idx] = hb;
        hloO[idx] = __float2bfloat16(h - __bfloat162float(hb));
    }
}

// pred = h @ dense_w + dense_b; h = hi + lo. One warp per batch row.
__global__ void dense_kernel(int cur, const float* __restrict__ dw,
                             const float* __restrict__ db,
                             float* __restrict__ out_t)
{
    const int gwarp = (blockIdx.x * blockDim.x + threadIdx.x) >> 5;
    const int lane = threadIdx.x & 31;
    if (gwarp >= BATCH) return;
    const __nv_bfloat16* __restrict__ hh = g_hhi[cur] + (size_t)gwarp * UNITS;
    const __nv_bfloat16* __restrict__ hl = g_hlo[cur] + (size_t)gwarp * UNITS;
    float s0 = 0.f, s1 = 0.f, s2 = 0.f;
    for (int u = lane; u < UNITS; u += 32) {
        const float hv = __bfloat162float(hh[u]) + __bfloat162float(hl[u]);
        s0 = fmaf(hv, dw[u * 3 + 0], s0);
        s1 = fmaf(hv, dw[u * 3 + 1], s1);
        s2 = fmaf(hv, dw[u * 3 + 2], s2);
    }
#pragma unroll
    for (int o = 16; o; o >>= 1) {
        s0 += __shfl_down_sync(0xffffffffu, s0, o);
        s1 += __shfl_down_sync(0xffffffffu, s1, o);
        s2 += __shfl_down_sync(0xffffffffu, s2, o);
    }
    if (lane == 0) {
        const float p0 = s0 + db[0];
        const float p1 = s1 + db[1];
        const float p2 = s2 + db[2];
        out_t[gwarp * 3 + 0] = p0;
        out_t[gwarp * 3 + 1] = p1;
        out_t[gwarp * 3 + 2] = p2;
        g_pred[gwarp * 3 + 0] = p0;
        g_pred[gwarp * 3 + 1] = p1;
        g_pred[gwarp * 3 + 2] = p2;
    }
}

extern "C" void kernel_launch(void* const* d_in, const int* in_sizes, int n_in,
                              void* d_out, int out_size) {
    const float* inputs = (const float*)d_in[0];  // [B, S, F]
    const float* wk     = (const float*)d_in[1];  // [F, 4U]
    const float* wr     = (const float*)d_in[2];  // [U, 4U]
    const float* bias   = (const float*)d_in[3];  // [4U]
    const float* dw     = (const float*)d_in[4];  // [U, F]
    const float* db     = (const float*)d_in[5];  // [F]
    float* out = (float*)d_out;                   // [OUT_NOTES, B, F]

    cudaFuncSetAttribute(lstm_mma_kernel, cudaFuncAttributeMaxDynamicSharedMemorySize, SMEM_BYTES);

    float* pred_ptr = nullptr;
    cudaGetSymbolAddress((void**)&pred_ptr, g_pred);

    prep_w_kernel<<<(ZCOLS * UNITS + 255) / 256, 256>>>(wr);
    zero_state_kernel<<<256, 256>>>();

    const dim3 grid(BATCH / BM, ZCOLS / BN);   // 16 x 8
    int cur = 0;
    for (int t = 0; t < SEQ; t++) {
        lstm_mma_kernel<<<grid, THREADS, SMEM_BYTES>>>(inputs + t * FEAT, SEQ * FEAT, wk, bias, cur);
        cur ^= 1;
    }
    dense_kernel<<<BATCH / 8, 256>>>(cur, dw, db, out);
    for (int t = 1; t < OUT_NOTES; t++) {
        lstm_mma_kernel<<<grid, THREADS, SMEM_BYTES>>>(pred_ptr, FEAT, wk, bias, cur);
        cur ^= 1;
        dense_kernel<<<BATCH / 8, 256>>>(cur, dw, db, out + (size_t)t * BATCH * FEAT);
    }
}